// round 10
// baseline (speedup 1.0000x reference)
#include <cuda_runtime.h>
#include <cuda_fp16.h>
#include <cstdint>

#define Bb 2
#define Cch 64
#define Dd 3
#define Nn 4096
#define Kk 16
#define Hh 256

// ---------------- device scratch ----------------
__device__ float  d_ptsT[Bb*Nn*Cch];
__device__ __half d_ptsTh[Bb*Nn*Cch];
__device__ float  d_sq[Bb*Nn];
__device__ int    d_idx[Bb*Kk*Nn];
__device__ float  d_AT[Cch*Hh];
__device__ __half d_BTh[Hh*Cch];          // [o][c]
__device__ __half d_W2h[Hh*Hh];           // [o][i]
__device__ __half d_W3h[Cch*Hh];          // [c][i]
__device__ __half d_U[Bb*Dd*Nn*Hh];
__device__ __half d_V[Bb*Kk*Nn*Hh];
__device__ float  d_pdist[Bb*8*16*Nn];
__device__ int    d_pidx[Bb*8*16*Nn];

// ---------------- helpers ----------------
__device__ __forceinline__ void mma_fp16(float* c, const uint32_t* a, uint32_t b0, uint32_t b1) {
    asm volatile("mma.sync.aligned.m16n8k16.row.col.f32.f16.f16.f32 "
        "{%0,%1,%2,%3}, {%4,%5,%6,%7}, {%8,%9}, {%0,%1,%2,%3};"
        : "+f"(c[0]), "+f"(c[1]), "+f"(c[2]), "+f"(c[3])
        : "r"(a[0]), "r"(a[1]), "r"(a[2]), "r"(a[3]), "r"(b0), "r"(b1));
}
__device__ __forceinline__ uint32_t ldh2(const __half* p) {
    return *(const uint32_t*)p;
}
__device__ __forceinline__ void ldmx4(uint32_t* r, uint32_t addr) {
    asm volatile("ldmatrix.sync.aligned.m8n8.x4.shared.b16 {%0,%1,%2,%3}, [%4];"
        : "=r"(r[0]), "=r"(r[1]), "=r"(r[2]), "=r"(r[3]) : "r"(addr));
}

// ---------------- weight prep ----------------
__global__ void prep_w(const float* __restrict__ W1) {
    int e = blockIdx.x * 256 + threadIdx.x;          // 16384
    if (e < Cch*Hh) {
        int c = e / Hh, o = e % Hh;
        float wc = W1[o*128 + c];
        float wn = W1[o*128 + 64 + c];
        d_AT[c*Hh + o] = wc - wn;
        d_BTh[o*Cch + c] = __float2half_rn(wn);
    }
}

__global__ void prep_w23(const float* __restrict__ W2, const float* __restrict__ W3) {
    int e = blockIdx.x * 256 + threadIdx.x;          // 81920
    if (e < 65536)      d_W2h[e] = __float2half_rn(W2[e]);
    else if (e < 81920) d_W3h[e - 65536] = __float2half_rn(W3[e - 65536]);
}

// mean over D + transpose + half copy, fused
__global__ void mean_k(const float* __restrict__ x) {
    int e = blockIdx.x * 256 + threadIdx.x;          // 524288
    int b = e >> 18;
    int cn = e & 262143;
    int c = cn >> 12, n = cn & 4095;
    int base = ((b*Cch + c)*Dd)*Nn + n;
    float v = (x[base] + x[base + Nn] + x[base + 2*Nn]) * (1.0f/3.0f);
    d_ptsT[(b*Nn + n)*Cch + c] = v;
    d_ptsTh[(b*Nn + n)*Cch + c] = __float2half_rn(v);
}

__global__ void sq_k() {
    int i = blockIdx.x * 256 + threadIdx.x;
    const float4* p = (const float4*)(d_ptsT + i*64);
    float s = 0.f;
#pragma unroll
    for (int t = 0; t < 16; t++) {
        float4 v = p[t];
        s += v.x*v.x + v.y*v.y + v.z*v.z + v.w*v.w;
    }
    d_sq[i] = s;
}

// ---------------- KNN part: 8-way candidate split ----------------
__global__ void knn_part() {
    __shared__ float rs[128*64];
    __shared__ float rsq[128];
    int bx = blockIdx.x;                 // 512 = 2b * 32qt * 8js
    int js = bx & 7;
    int qt = (bx >> 3) & 31;
    int b  = bx >> 8;
    int n  = qt*128 + threadIdx.x;

    float q[64];
    const float4* qp = (const float4*)(d_ptsT + (b*Nn + n)*64);
#pragma unroll
    for (int t = 0; t < 16; t++) {
        float4 v = qp[t];
        q[4*t] = v.x; q[4*t+1] = v.y; q[4*t+2] = v.z; q[4*t+3] = v.w;
    }
    float sqn = d_sq[b*Nn + n];

    float dist[16]; int ind[16];
#pragma unroll
    for (int s = 0; s < 16; s++) { dist[s] = __int_as_float(0x7f800000); ind[s] = 0; }

    for (int jt = js*4; jt < js*4 + 4; jt++) {
        __syncthreads();
        const float4* src = (const float4*)(d_ptsT + (b*Nn + jt*128)*64);
        for (int e = threadIdx.x; e < 2048; e += 128)
            ((float4*)rs)[e] = src[e];
        rsq[threadIdx.x] = d_sq[b*Nn + jt*128 + threadIdx.x];
        __syncthreads();

#pragma unroll 2
        for (int r = 0; r < 128; r++) {
            int j = jt*128 + r;
            float a0 = 0.f, a1 = 0.f, a2 = 0.f, a3 = 0.f;
            const float4* rv = (const float4*)(rs + r*64);
#pragma unroll
            for (int t = 0; t < 16; t++) {
                float4 v = rv[t];
                a0 = fmaf(q[4*t],   v.x, a0);
                a1 = fmaf(q[4*t+1], v.y, a1);
                a2 = fmaf(q[4*t+2], v.z, a2);
                a3 = fmaf(q[4*t+3], v.w, a3);
            }
            float d2 = sqn + rsq[r] - 2.0f*((a0+a1)+(a2+a3));
            if (j == n) continue;
            if (d2 < dist[15]) {
                float dd = d2; int jj = j;
#pragma unroll
                for (int s = 0; s < 16; s++) {
                    if (dd < dist[s]) {
                        float td = dist[s]; int ti = ind[s];
                        dist[s] = dd; ind[s] = jj;
                        dd = td; jj = ti;
                    }
                }
            }
        }
    }
#pragma unroll
    for (int s = 0; s < 16; s++) {
        int o = ((b*8 + js)*16 + s)*Nn + n;
        d_pdist[o] = dist[s];
        d_pidx[o]  = ind[s];
    }
}

__global__ void knn_merge() {
    int e = blockIdx.x * 256 + threadIdx.x;     // 8192
    int b = e >> 12, n = e & 4095;

    float dist[16]; int ind[16];
#pragma unroll
    for (int s = 0; s < 16; s++) { dist[s] = __int_as_float(0x7f800000); ind[s] = 0; }

    for (int js = 0; js < 8; js++) {
#pragma unroll
        for (int s = 0; s < 16; s++) {
            int o = ((b*8 + js)*16 + s)*Nn + n;
            float dd = d_pdist[o];
            int jj = d_pidx[o];
            if (dd < dist[15]) {
#pragma unroll
                for (int t = 0; t < 16; t++) {
                    if (dd < dist[t]) {
                        float td = dist[t]; int ti = ind[t];
                        dist[t] = dd; ind[t] = jj;
                        dd = td; jj = ti;
                    }
                }
            }
        }
    }
#pragma unroll
    for (int s = 0; s < 16; s++)
        d_idx[(b*Kk + s)*Nn + n] = ind[s];
}

// ---------------- U kernel (fp32 FFMA, small) ----------------
__global__ __launch_bounds__(256) void u_kern(const float* __restrict__ x,
                                              const float* __restrict__ b1) {
    extern __shared__ float sm[];
    float* Ws = sm;
    float* xs = sm + 16384;
    int bx = blockIdx.x;
    int ng = bx & 127;
    int d  = (bx >> 7) % 3;
    int b  = bx / 384;
    int n0 = ng * 32;

    for (int e = threadIdx.x; e < 4096; e += 256)
        ((float4*)Ws)[e] = ((const float4*)d_AT)[e];
    for (int e = threadIdx.x; e < 2048; e += 256) {
        int c = e >> 5, p = e & 31;
        xs[c*36 + p] = x[((b*Cch + c)*Dd + d)*Nn + n0 + p];
    }
    __syncthreads();

    int o = threadIdx.x;
    float acc[32];
#pragma unroll
    for (int p = 0; p < 32; p++) acc[p] = 0.f;
#pragma unroll 4
    for (int c = 0; c < 64; c++) {
        float w = Ws[c*256 + o];
        const float4* xv = (const float4*)(xs + c*36);
#pragma unroll
        for (int p4 = 0; p4 < 8; p4++) {
            float4 v = xv[p4];
            acc[4*p4+0] = fmaf(w, v.x, acc[4*p4+0]);
            acc[4*p4+1] = fmaf(w, v.y, acc[4*p4+1]);
            acc[4*p4+2] = fmaf(w, v.z, acc[4*p4+2]);
            acc[4*p4+3] = fmaf(w, v.w, acc[4*p4+3]);
        }
    }
    float bb = b1[o];
    __half* dst = d_U + (((b*Dd + d)*Nn) + n0)*Hh + o;
#pragma unroll
    for (int p = 0; p < 32; p++) dst[p*Hh] = __float2half_rn(acc[p] + bb);
}

// ---------------- V via fp16 mma ----------------
__global__ __launch_bounds__(256) void v_mma() {
    extern __shared__ __half smh[];
    __shared__ int sidx[128];
    __half* As = smh;                     // stride 72
    __half* Bs = smh + 9216;              // stride 72
    int tid = threadIdx.x;
    int wid = tid >> 5, lid = tid & 31;
    int row = lid >> 2, tg = lid & 3;

    int bx = blockIdx.x;                  // 1024 = 2b * 512
    int ng = bx & 511;
    int b  = bx >> 9;
    int n0 = ng * 8;

    if (tid < 128) {
        int nl = tid >> 4, kk = tid & 15;
        sidx[tid] = d_idx[(b*16 + kk)*4096 + n0 + nl];
    }
    for (int e = tid; e < 2048; e += 256) {
        int o = e >> 3, iv = e & 7;
        *(uint4*)(Bs + o*72 + iv*8) = *(const uint4*)(d_BTh + o*64 + iv*8);
    }
    __syncthreads();
    for (int e = tid; e < 2048; e += 256) {
        int p = e >> 4, hv = e & 15;
        *(uint2*)(As + p*72 + hv*4) = *(const uint2*)(d_ptsTh + (b*4096 + sidx[p])*64 + hv*4);
    }
    __syncthreads();

    int pb = (wid & 1) * 64;
    int ob = (wid >> 1) * 64;
    float acc[4][8][4];
#pragma unroll
    for (int mi = 0; mi < 4; mi++)
#pragma unroll
        for (int ni = 0; ni < 8; ni++)
#pragma unroll
            for (int r = 0; r < 4; r++) acc[mi][ni][r] = 0.f;

#pragma unroll
    for (int ks = 0; ks < 4; ks++) {
        int kb = ks*16;
        uint32_t a[4][4];
#pragma unroll
        for (int mi = 0; mi < 4; mi++) {
            int p0 = pb + mi*16 + row;
            a[mi][0] = ldh2(As + p0*72 + kb + 2*tg);
            a[mi][1] = ldh2(As + (p0+8)*72 + kb + 2*tg);
            a[mi][2] = ldh2(As + p0*72 + kb + 2*tg + 8);
            a[mi][3] = ldh2(As + (p0+8)*72 + kb + 2*tg + 8);
        }
        uint32_t bq[8][2];
#pragma unroll
        for (int ni = 0; ni < 8; ni++) {
            int o = ob + ni*8 + row;
            bq[ni][0] = ldh2(Bs + o*72 + kb + 2*tg);
            bq[ni][1] = ldh2(Bs + o*72 + kb + 2*tg + 8);
        }
#pragma unroll
        for (int mi = 0; mi < 4; mi++)
#pragma unroll
            for (int ni = 0; ni < 8; ni++)
                mma_fp16(acc[mi][ni], a[mi], bq[ni][0], bq[ni][1]);
    }

#pragma unroll
    for (int mi = 0; mi < 4; mi++) {
        int p0 = pb + mi*16 + row;
#pragma unroll
        for (int half_ = 0; half_ < 2; half_++) {
            int p = p0 + half_*8;
            int nl = p >> 4, kk = p & 15;
            __half* dst = d_V + ((b*16 + kk)*4096 + n0 + nl)*256;
#pragma unroll
            for (int ni = 0; ni < 8; ni++) {
                int o = ob + ni*8 + 2*tg;
                float c0 = acc[mi][ni][half_*2 + 0];
                float c1 = acc[mi][ni][half_*2 + 1];
                *(__half2*)(dst + o) = __floats2half2_rn(c0, c1);
            }
        }
    }
}

// ---------------- fp16 mma fused layer2+layer3+max+residual (64-pt CTAs, 2/SM) ----------------
// SMEM bytes:
//   h1/h2 : [64][264] half @0        (33792)
//   BUF   : 2 x [256][40] half @33792 (40960)  | W3s [64][264] half | r [64][66] f32
//   b2s f32 @74752 (1024) ; b3s f32 @75776 (256) ; TOT 76032
#define SMB_BUF 33792
#define SMB_B2  74752
#define SMB_B3  75776
#define SMB_TOT 76032

__global__ __launch_bounds__(256, 2) void mlp2_mma(const float* __restrict__ x,
                                                   const float* __restrict__ b2,
                                                   const float* __restrict__ b3,
                                                   float* __restrict__ out) {
    extern __shared__ char smem[];
    __half* smh = (__half*)smem;
    float* b2s = (float*)(smem + SMB_B2);
    float* b3s = (float*)(smem + SMB_B3);
    uint32_t sbase = (uint32_t)__cvta_generic_to_shared(smem);
    int tid = threadIdx.x;
    int wid = tid >> 5, lid = tid & 31;
    int row = lid >> 2, tg = lid & 3;
    int lm  = lid & 15, lh = lid >> 4;    // ldmatrix row / col-half

    int bx = blockIdx.x;                  // 6144 = 2*3*1024
    int ng = bx & 1023;
    int d  = (bx >> 10) % 3;
    int b  = bx / 3072;
    int n0 = ng * 4;

    if (tid < 256) b2s[tid] = b2[tid];
    if (tid < 64)  b3s[tid] = b3[tid];

    // ---- h1 = relu(U+V) in half, [64 p][264] ----
    {
        const uint4* Vp = (const uint4*)d_V;
        const uint4* Up = (const uint4*)d_U;
        for (int e = tid; e < 2048; e += 256) {
            int p = e >> 5, iv = e & 31;
            int nl = p >> 4, kk = p & 15;
            uint4 v = Vp[((b*16 + kk)*4096 + n0 + nl)*32 + iv];
            uint4 u = Up[((b*3  + d )*4096 + n0 + nl)*32 + iv];
            __half2 z = __float2half2_rn(0.f);
            uint4 h;
            *(__half2*)&h.x = __hmax2(__hadd2(*(__half2*)&u.x, *(__half2*)&v.x), z);
            *(__half2*)&h.y = __hmax2(__hadd2(*(__half2*)&u.y, *(__half2*)&v.y), z);
            *(__half2*)&h.z = __hmax2(__hadd2(*(__half2*)&u.z, *(__half2*)&v.z), z);
            *(__half2*)&h.w = __hmax2(__hadd2(*(__half2*)&u.w, *(__half2*)&v.w), z);
            *(uint4*)(smh + p*264 + iv*8) = h;
        }
    }

    // ---- GEMM1: D[64p][256o] = h1 . W2^T (K=256, chunks of 32) ----
    int wm = wid & 1, wn = wid >> 1;
    int pb = wm * 32, ob = wn * 64;

    float acc[2][8][4];
#pragma unroll
    for (int mi = 0; mi < 2; mi++)
#pragma unroll
        for (int ni = 0; ni < 8; ni++)
#pragma unroll
            for (int r = 0; r < 4; r++) acc[mi][ni][r] = 0.f;

    const uint4* W2v = (const uint4*)d_W2h;    // 32 uint4 per o-row
    uint4 g[4];
#pragma unroll
    for (int j = 0; j < 4; j++) g[j] = W2v[tid*32 + j];

    for (int ch = 0; ch < 8; ch++) {
        int buf = ch & 1;
        __half* Bsw = smh + SMB_BUF/2 + buf*10240;
#pragma unroll
        for (int j = 0; j < 4; j++)
            *(uint4*)(Bsw + tid*40 + j*8) = g[j];
        __syncthreads();
        if (ch < 7) {
#pragma unroll
            for (int j = 0; j < 4; j++) g[j] = W2v[tid*32 + (ch+1)*4 + j];
        }
        uint32_t bufb = sbase + SMB_BUF + buf*20480;
#pragma unroll
        for (int k16 = 0; k16 < 2; k16++) {
            int kb = ch*32 + k16*16;
            int kl = k16*16;
            uint32_t a[2][4];
#pragma unroll
            for (int mi = 0; mi < 2; mi++) {
                uint32_t aa = sbase + ((pb + mi*16 + lm)*264 + kb + lh*8)*2;
                ldmx4(a[mi], aa);
            }
            uint32_t bb[4][4];
#pragma unroll
            for (int nj = 0; nj < 4; nj++) {
                uint32_t ba = bufb + ((ob + nj*16 + lm)*40 + kl + lh*8)*2;
                ldmx4(bb[nj], ba);
            }
#pragma unroll
            for (int mi = 0; mi < 2; mi++)
#pragma unroll
                for (int nj = 0; nj < 4; nj++) {
                    mma_fp16(acc[mi][2*nj],   a[mi], bb[nj][0], bb[nj][2]);
                    mma_fp16(acc[mi][2*nj+1], a[mi], bb[nj][1], bb[nj][3]);
                }
        }
        __syncthreads();
    }

    // ---- epilogue1: h2 = relu(D + b2) -> half, back into h1 region ----
#pragma unroll
    for (int mi = 0; mi < 2; mi++) {
#pragma unroll
        for (int ni = 0; ni < 8; ni++) {
            int p = pb + mi*16 + row;
            int o = ob + ni*8 + 2*tg;
            float bo0 = b2s[o], bo1 = b2s[o+1];
            float v00 = fmaxf(acc[mi][ni][0] + bo0, 0.f);
            float v01 = fmaxf(acc[mi][ni][1] + bo1, 0.f);
            float v10 = fmaxf(acc[mi][ni][2] + bo0, 0.f);
            float v11 = fmaxf(acc[mi][ni][3] + bo1, 0.f);
            *(__half2*)(smh + p*264 + o)     = __floats2half2_rn(v00, v01);
            *(__half2*)(smh + (p+8)*264 + o) = __floats2half2_rn(v10, v11);
        }
    }
    __syncthreads();

    // ---- stage W3h [64c][264] into BUF region ----
    {
        __half* W3s = smh + SMB_BUF/2;
        for (int e = tid; e < 2048; e += 256) {
            int c = e >> 5, iv = e & 31;
            *(uint4*)(W3s + c*264 + iv*8) = *(const uint4*)(d_W3h + c*256 + iv*8);
        }
    }
    __syncthreads();

    // ---- GEMM2: D2[64p][64c] = h2 . W3^T (K=256) ----
    int pb2 = (wid & 1) * 32;
    int cb  = (wid >> 1) * 16;
    float ac2[2][2][4];
#pragma unroll
    for (int mi = 0; mi < 2; mi++)
#pragma unroll
        for (int ni = 0; ni < 2; ni++)
#pragma unroll
            for (int r = 0; r < 4; r++) ac2[mi][ni][r] = 0.f;

    uint32_t w3b = sbase + SMB_BUF;
#pragma unroll 4
    for (int ks = 0; ks < 16; ks++) {
        int kb = ks*16;
        uint32_t a[2][4];
#pragma unroll
        for (int mi = 0; mi < 2; mi++) {
            uint32_t aa = sbase + ((pb2 + mi*16 + lm)*264 + kb + lh*8)*2;
            ldmx4(a[mi], aa);
        }
        uint32_t bb[4];
        {
            uint32_t ba = w3b + ((cb + lm)*264 + kb + lh*8)*2;
            ldmx4(bb, ba);
        }
#pragma unroll
        for (int mi = 0; mi < 2; mi++) {
            mma_fp16(ac2[mi][0], a[mi], bb[0], bb[2]);
            mma_fp16(ac2[mi][1], a[mi], bb[1], bb[3]);
        }
    }
    __syncthreads();

    // ---- stage r = D2 -> BUF region as f32 [64 p][66] ----
    {
        float* rsm = (float*)(smem + SMB_BUF);
#pragma unroll
        for (int mi = 0; mi < 2; mi++) {
#pragma unroll
            for (int ni = 0; ni < 2; ni++) {
                int p = pb2 + mi*16 + row;
                int c = cb + ni*8 + 2*tg;
                *(float2*)(rsm + p*66 + c)     = make_float2(ac2[mi][ni][0], ac2[mi][ni][1]);
                *(float2*)(rsm + (p+8)*66 + c) = make_float2(ac2[mi][ni][2], ac2[mi][ni][3]);
            }
        }
    }
    __syncthreads();

    // ---- max over k + bias + residual ----
    {
        const float* rsm = (const float*)(smem + SMB_BUF);
        for (int e = tid; e < 256; e += 256) {
            int nl = e >> 6, c = e & 63;
            float m = -3.4e38f;
#pragma unroll
            for (int kk = 0; kk < 16; kk++)
                m = fmaxf(m, rsm[(nl*16 + kk)*66 + c]);
            int oi = ((b*64 + c)*3 + d)*4096 + n0 + nl;
            out[oi] = m + b3s[c] + x[oi];
        }
    }
}

// ---------------- launch ----------------
extern "C" void kernel_launch(void* const* d_in, const int* in_sizes, int n_in,
                              void* d_out, int out_size) {
    const float* x  = (const float*)d_in[0];
    const float* W1 = (const float*)d_in[1];
    const float* b1 = (const float*)d_in[2];
    const float* W2 = (const float*)d_in[3];
    const float* b2 = (const float*)d_in[4];
    const float* W3 = (const float*)d_in[5];
    const float* b3 = (const float*)d_in[6];
    float* out = (float*)d_out;

    static bool attr_done = false;
    if (!attr_done) {
        cudaFuncSetAttribute(u_kern,   cudaFuncAttributeMaxDynamicSharedMemorySize, 74752);
        cudaFuncSetAttribute(v_mma,    cudaFuncAttributeMaxDynamicSharedMemorySize, 55296);
        cudaFuncSetAttribute(mlp2_mma, cudaFuncAttributeMaxDynamicSharedMemorySize, SMB_TOT);
        attr_done = true;
    }

    prep_w<<<64, 256>>>(W1);
    prep_w23<<<320, 256>>>(W2, W3);
    mean_k<<<2048, 256>>>(x);
    sq_k<<<32, 256>>>();
    knn_part<<<512, 128>>>();
    knn_merge<<<32, 256>>>();
    u_kern<<<768, 256, 74752>>>(x, b1);
    v_mma<<<1024, 256, 55296>>>();
    mlp2_mma<<<6144, 256, SMB_TOT>>>(x, b2, b3, out);
}

// round 14
// speedup vs baseline: 1.1372x; 1.1372x over previous
#include <cuda_runtime.h>
#include <cuda_fp16.h>
#include <cstdint>

#define Bb 2
#define Cch 64
#define Dd 3
#define Nn 4096
#define Kk 16
#define Hh 256

// ---------------- device scratch ----------------
__device__ float  d_ptsT[Bb*Nn*Cch];
__device__ __half d_ptsTh[Bb*Nn*Cch];
__device__ float  d_sq[Bb*Nn];
__device__ int    d_idx[Bb*Kk*Nn];
__device__ float  d_AT[Cch*Hh];
__device__ __half d_BTh[Hh*Cch];          // [o][c]
__device__ __half d_W2h[Hh*Hh];           // [o][i]
__device__ __half d_W3h[Cch*Hh];          // [c][i]
__device__ __half d_U[Bb*Dd*Nn*Hh];
__device__ __half d_V[Bb*Kk*Nn*Hh];
__device__ float  d_pdist[Bb*8*16*Nn];
__device__ int    d_pidx[Bb*8*16*Nn];

// ---------------- helpers ----------------
__device__ __forceinline__ void mma_fp16(float* c, const uint32_t* a, uint32_t b0, uint32_t b1) {
    asm volatile("mma.sync.aligned.m16n8k16.row.col.f32.f16.f16.f32 "
        "{%0,%1,%2,%3}, {%4,%5,%6,%7}, {%8,%9}, {%0,%1,%2,%3};"
        : "+f"(c[0]), "+f"(c[1]), "+f"(c[2]), "+f"(c[3])
        : "r"(a[0]), "r"(a[1]), "r"(a[2]), "r"(a[3]), "r"(b0), "r"(b1));
}
__device__ __forceinline__ uint32_t ldh2(const __half* p) {
    return *(const uint32_t*)p;
}
__device__ __forceinline__ void ldmx4(uint32_t* r, uint32_t addr) {
    asm volatile("ldmatrix.sync.aligned.m8n8.x4.shared.b16 {%0,%1,%2,%3}, [%4];"
        : "=r"(r[0]), "=r"(r[1]), "=r"(r[2]), "=r"(r[3]) : "r"(addr));
}
__device__ __forceinline__ void cpa16(uint32_t dst, const void* src) {
    asm volatile("cp.async.ca.shared.global [%0], [%1], 16;" :: "r"(dst), "l"(src));
}
#define CP_COMMIT() asm volatile("cp.async.commit_group;" ::: "memory")
#define CP_WAIT(N)  asm volatile("cp.async.wait_group %0;" :: "n"(N) : "memory")

// ---------------- weight prep ----------------
__global__ void prep_w(const float* __restrict__ W1) {
    int e = blockIdx.x * 256 + threadIdx.x;          // 16384
    if (e < Cch*Hh) {
        int c = e / Hh, o = e % Hh;
        float wc = W1[o*128 + c];
        float wn = W1[o*128 + 64 + c];
        d_AT[c*Hh + o] = wc - wn;
        d_BTh[o*Cch + c] = __float2half_rn(wn);
    }
}

__global__ void prep_w23(const float* __restrict__ W2, const float* __restrict__ W3) {
    int e = blockIdx.x * 256 + threadIdx.x;          // 81920
    if (e < 65536)      d_W2h[e] = __float2half_rn(W2[e]);
    else if (e < 81920) d_W3h[e - 65536] = __float2half_rn(W3[e - 65536]);
}

// mean over D + transpose + half copy, fused
__global__ void mean_k(const float* __restrict__ x) {
    int e = blockIdx.x * 256 + threadIdx.x;          // 524288
    int b = e >> 18;
    int cn = e & 262143;
    int c = cn >> 12, n = cn & 4095;
    int base = ((b*Cch + c)*Dd)*Nn + n;
    float v = (x[base] + x[base + Nn] + x[base + 2*Nn]) * (1.0f/3.0f);
    d_ptsT[(b*Nn + n)*Cch + c] = v;
    d_ptsTh[(b*Nn + n)*Cch + c] = __float2half_rn(v);
}

__global__ void sq_k() {
    int i = blockIdx.x * 256 + threadIdx.x;
    const float4* p = (const float4*)(d_ptsT + i*64);
    float s = 0.f;
#pragma unroll
    for (int t = 0; t < 16; t++) {
        float4 v = p[t];
        s += v.x*v.x + v.y*v.y + v.z*v.z + v.w*v.w;
    }
    d_sq[i] = s;
}

// ---------------- KNN part: 8-way candidate split ----------------
__global__ void knn_part() {
    __shared__ float rs[128*64];
    __shared__ float rsq[128];
    int bx = blockIdx.x;                 // 512 = 2b * 32qt * 8js
    int js = bx & 7;
    int qt = (bx >> 3) & 31;
    int b  = bx >> 8;
    int n  = qt*128 + threadIdx.x;

    float q[64];
    const float4* qp = (const float4*)(d_ptsT + (b*Nn + n)*64);
#pragma unroll
    for (int t = 0; t < 16; t++) {
        float4 v = qp[t];
        q[4*t] = v.x; q[4*t+1] = v.y; q[4*t+2] = v.z; q[4*t+3] = v.w;
    }
    float sqn = d_sq[b*Nn + n];

    float dist[16]; int ind[16];
#pragma unroll
    for (int s = 0; s < 16; s++) { dist[s] = __int_as_float(0x7f800000); ind[s] = 0; }

    for (int jt = js*4; jt < js*4 + 4; jt++) {
        __syncthreads();
        const float4* src = (const float4*)(d_ptsT + (b*Nn + jt*128)*64);
        for (int e = threadIdx.x; e < 2048; e += 128)
            ((float4*)rs)[e] = src[e];
        rsq[threadIdx.x] = d_sq[b*Nn + jt*128 + threadIdx.x];
        __syncthreads();

#pragma unroll 2
        for (int r = 0; r < 128; r++) {
            int j = jt*128 + r;
            float a0 = 0.f, a1 = 0.f, a2 = 0.f, a3 = 0.f;
            const float4* rv = (const float4*)(rs + r*64);
#pragma unroll
            for (int t = 0; t < 16; t++) {
                float4 v = rv[t];
                a0 = fmaf(q[4*t],   v.x, a0);
                a1 = fmaf(q[4*t+1], v.y, a1);
                a2 = fmaf(q[4*t+2], v.z, a2);
                a3 = fmaf(q[4*t+3], v.w, a3);
            }
            float d2 = sqn + rsq[r] - 2.0f*((a0+a1)+(a2+a3));
            if (j == n) continue;
            if (d2 < dist[15]) {
                float dd = d2; int jj = j;
#pragma unroll
                for (int s = 0; s < 16; s++) {
                    if (dd < dist[s]) {
                        float td = dist[s]; int ti = ind[s];
                        dist[s] = dd; ind[s] = jj;
                        dd = td; jj = ti;
                    }
                }
            }
        }
    }
#pragma unroll
    for (int s = 0; s < 16; s++) {
        int o = ((b*8 + js)*16 + s)*Nn + n;
        d_pdist[o] = dist[s];
        d_pidx[o]  = ind[s];
    }
}

__global__ void knn_merge() {
    int e = blockIdx.x * 256 + threadIdx.x;     // 8192
    int b = e >> 12, n = e & 4095;

    float dist[16]; int ind[16];
#pragma unroll
    for (int s = 0; s < 16; s++) { dist[s] = __int_as_float(0x7f800000); ind[s] = 0; }

    for (int js = 0; js < 8; js++) {
#pragma unroll
        for (int s = 0; s < 16; s++) {
            int o = ((b*8 + js)*16 + s)*Nn + n;
            float dd = d_pdist[o];
            int jj = d_pidx[o];
            if (dd < dist[15]) {
#pragma unroll
                for (int t = 0; t < 16; t++) {
                    if (dd < dist[t]) {
                        float td = dist[t]; int ti = ind[t];
                        dist[t] = dd; ind[t] = jj;
                        dd = td; jj = ti;
                    }
                }
            }
        }
    }
#pragma unroll
    for (int s = 0; s < 16; s++)
        d_idx[(b*Kk + s)*Nn + n] = ind[s];
}

// ---------------- U kernel (fp32 FFMA, small) ----------------
__global__ __launch_bounds__(256) void u_kern(const float* __restrict__ x,
                                              const float* __restrict__ b1) {
    extern __shared__ float sm[];
    float* Ws = sm;
    float* xs = sm + 16384;
    int bx = blockIdx.x;
    int ng = bx & 127;
    int d  = (bx >> 7) % 3;
    int b  = bx / 384;
    int n0 = ng * 32;

    for (int e = threadIdx.x; e < 4096; e += 256)
        ((float4*)Ws)[e] = ((const float4*)d_AT)[e];
    for (int e = threadIdx.x; e < 2048; e += 256) {
        int c = e >> 5, p = e & 31;
        xs[c*36 + p] = x[((b*Cch + c)*Dd + d)*Nn + n0 + p];
    }
    __syncthreads();

    int o = threadIdx.x;
    float acc[32];
#pragma unroll
    for (int p = 0; p < 32; p++) acc[p] = 0.f;
#pragma unroll 4
    for (int c = 0; c < 64; c++) {
        float w = Ws[c*256 + o];
        const float4* xv = (const float4*)(xs + c*36);
#pragma unroll
        for (int p4 = 0; p4 < 8; p4++) {
            float4 v = xv[p4];
            acc[4*p4+0] = fmaf(w, v.x, acc[4*p4+0]);
            acc[4*p4+1] = fmaf(w, v.y, acc[4*p4+1]);
            acc[4*p4+2] = fmaf(w, v.z, acc[4*p4+2]);
            acc[4*p4+3] = fmaf(w, v.w, acc[4*p4+3]);
        }
    }
    float bb = b1[o];
    __half* dst = d_U + (((b*Dd + d)*Nn) + n0)*Hh + o;
#pragma unroll
    for (int p = 0; p < 32; p++) dst[p*Hh] = __float2half_rn(acc[p] + bb);
}

// ---------------- V via fp16 mma ----------------
__global__ __launch_bounds__(256) void v_mma() {
    extern __shared__ __half smh[];
    __shared__ int sidx[128];
    __half* As = smh;                     // stride 72
    __half* Bs = smh + 9216;              // stride 72
    int tid = threadIdx.x;
    int wid = tid >> 5, lid = tid & 31;
    int row = lid >> 2, tg = lid & 3;

    int bx = blockIdx.x;                  // 1024 = 2b * 512
    int ng = bx & 511;
    int b  = bx >> 9;
    int n0 = ng * 8;

    if (tid < 128) {
        int nl = tid >> 4, kk = tid & 15;
        sidx[tid] = d_idx[(b*16 + kk)*4096 + n0 + nl];
    }
    for (int e = tid; e < 2048; e += 256) {
        int o = e >> 3, iv = e & 7;
        *(uint4*)(Bs + o*72 + iv*8) = *(const uint4*)(d_BTh + o*64 + iv*8);
    }
    __syncthreads();
    for (int e = tid; e < 2048; e += 256) {
        int p = e >> 4, hv = e & 15;
        *(uint2*)(As + p*72 + hv*4) = *(const uint2*)(d_ptsTh + (b*4096 + sidx[p])*64 + hv*4);
    }
    __syncthreads();

    int pb = (wid & 1) * 64;
    int ob = (wid >> 1) * 64;
    float acc[4][8][4];
#pragma unroll
    for (int mi = 0; mi < 4; mi++)
#pragma unroll
        for (int ni = 0; ni < 8; ni++)
#pragma unroll
            for (int r = 0; r < 4; r++) acc[mi][ni][r] = 0.f;

#pragma unroll
    for (int ks = 0; ks < 4; ks++) {
        int kb = ks*16;
        uint32_t a[4][4];
#pragma unroll
        for (int mi = 0; mi < 4; mi++) {
            int p0 = pb + mi*16 + row;
            a[mi][0] = ldh2(As + p0*72 + kb + 2*tg);
            a[mi][1] = ldh2(As + (p0+8)*72 + kb + 2*tg);
            a[mi][2] = ldh2(As + p0*72 + kb + 2*tg + 8);
            a[mi][3] = ldh2(As + (p0+8)*72 + kb + 2*tg + 8);
        }
        uint32_t bq[8][2];
#pragma unroll
        for (int ni = 0; ni < 8; ni++) {
            int o = ob + ni*8 + row;
            bq[ni][0] = ldh2(Bs + o*72 + kb + 2*tg);
            bq[ni][1] = ldh2(Bs + o*72 + kb + 2*tg + 8);
        }
#pragma unroll
        for (int mi = 0; mi < 4; mi++)
#pragma unroll
            for (int ni = 0; ni < 8; ni++)
                mma_fp16(acc[mi][ni], a[mi], bq[ni][0], bq[ni][1]);
    }

#pragma unroll
    for (int mi = 0; mi < 4; mi++) {
        int p0 = pb + mi*16 + row;
#pragma unroll
        for (int half_ = 0; half_ < 2; half_++) {
            int p = p0 + half_*8;
            int nl = p >> 4, kk = p & 15;
            __half* dst = d_V + ((b*16 + kk)*4096 + n0 + nl)*256;
#pragma unroll
            for (int ni = 0; ni < 8; ni++) {
                int o = ob + ni*8 + 2*tg;
                float c0 = acc[mi][ni][half_*2 + 0];
                float c1 = acc[mi][ni][half_*2 + 1];
                *(__half2*)(dst + o) = __floats2half2_rn(c0, c1);
            }
        }
    }
}

// ---------------- fp16 mma fused layer2+layer3+max+residual (128-pt, cp.async ring) ----------------
// SMEM bytes:
//   h1/h2 : [128][264] half @0            (67584)
//   BUF   : 3 x [256][72] half @67584     (110592)   | later r [128][66] f32
//   W3s   : [64][264] half @178176        (33792)
//   b2s f32 @211968 (1024) ; b3s f32 @212992 (256) ; TOT 213248
#define SMB_BUF 67584
#define SMB_W3  178176
#define SMB_B2  211968
#define SMB_B3  212992
#define SMB_TOT 213248

__global__ __launch_bounds__(256, 1) void mlp2_mma(const float* __restrict__ x,
                                                   const float* __restrict__ b2,
                                                   const float* __restrict__ b3,
                                                   float* __restrict__ out) {
    extern __shared__ char smem[];
    __half* smh = (__half*)smem;
    float* b2s = (float*)(smem + SMB_B2);
    float* b3s = (float*)(smem + SMB_B3);
    uint32_t sbase = (uint32_t)__cvta_generic_to_shared(smem);
    int tid = threadIdx.x;
    int wid = tid >> 5, lid = tid & 31;
    int row = lid >> 2, tg = lid & 3;
    int lm  = lid & 15, lh = lid >> 4;    // ldmatrix row / col-half

    int bx = blockIdx.x;                  // 3072 = 2*3*512
    int ng = bx & 511;
    int d  = (bx >> 9) % 3;
    int b  = bx / 1536;
    int n0 = ng * 8;

    if (tid < 256) b2s[tid] = b2[tid];
    if (tid < 64)  b3s[tid] = b3[tid];

    // ---- prologue cp.async: chunk0 (G0), W3 (G1), chunk1 (G2) ----
    {
        // chunk 0 -> buf 0
#pragma unroll
        for (int it = 0; it < 8; it++) {
            int e = tid + it*256;
            int o = e >> 3, j = e & 7;
            cpa16(sbase + SMB_BUF + (o*72 + j*8)*2, d_W2h + o*256 + 0*64 + j*8);
        }
        CP_COMMIT();
        // W3 -> W3s  (FULL 256-half rows: 32 x 16B per row)
#pragma unroll
        for (int it = 0; it < 8; it++) {
            int e = tid + it*256;
            int c = e >> 5, j = e & 31;
            cpa16(sbase + SMB_W3 + (c*264 + j*8)*2, d_W3h + c*256 + j*8);
        }
        CP_COMMIT();
        // chunk 1 -> buf 1
#pragma unroll
        for (int it = 0; it < 8; it++) {
            int e = tid + it*256;
            int o = e >> 3, j = e & 7;
            cpa16(sbase + SMB_BUF + 36864 + (o*72 + j*8)*2, d_W2h + o*256 + 1*64 + j*8);
        }
        CP_COMMIT();
    }

    // ---- h1 = relu(U+V) in half, [128 p][264] ----
    {
        const uint4* Vp = (const uint4*)d_V;
        const uint4* Up = (const uint4*)d_U;
        for (int e = tid; e < 4096; e += 256) {
            int p = e >> 5, iv = e & 31;
            int nl = p >> 4, kk = p & 15;
            uint4 v = Vp[((b*16 + kk)*4096 + n0 + nl)*32 + iv];
            uint4 u = Up[((b*3  + d )*4096 + n0 + nl)*32 + iv];
            __half2 z = __float2half2_rn(0.f);
            uint4 h;
            *(__half2*)&h.x = __hmax2(__hadd2(*(__half2*)&u.x, *(__half2*)&v.x), z);
            *(__half2*)&h.y = __hmax2(__hadd2(*(__half2*)&u.y, *(__half2*)&v.y), z);
            *(__half2*)&h.z = __hmax2(__hadd2(*(__half2*)&u.z, *(__half2*)&v.z), z);
            *(__half2*)&h.w = __hmax2(__hadd2(*(__half2*)&u.w, *(__half2*)&v.w), z);
            *(uint4*)(smh + p*264 + iv*8) = h;
        }
    }

    // ---- GEMM1: D[128p][256o] = h1 . W2^T (K=256, 4 chunks of 64, 3-buffer ring) ----
    int pb = (wid & 1) * 64;
    int ob = (wid >> 1) * 64;

    float acc[4][8][4];
#pragma unroll
    for (int mi = 0; mi < 4; mi++)
#pragma unroll
        for (int ni = 0; ni < 8; ni++)
#pragma unroll
            for (int r = 0; r < 4; r++) acc[mi][ni][r] = 0.f;

#pragma unroll
    for (int ch = 0; ch < 4; ch++) {
        if (ch == 0)      CP_WAIT(2);
        else if (ch < 3)  CP_WAIT(1);
        else              CP_WAIT(0);
        __syncthreads();
        if (ch < 2) {
            int cn = ch + 2;
            uint32_t dstb = sbase + SMB_BUF + (cn % 3)*36864;
#pragma unroll
            for (int it = 0; it < 8; it++) {
                int e = tid + it*256;
                int o = e >> 3, j = e & 7;
                cpa16(dstb + (o*72 + j*8)*2, d_W2h + o*256 + cn*64 + j*8);
            }
            CP_COMMIT();
        }
        uint32_t bufb = sbase + SMB_BUF + (ch % 3)*36864;
#pragma unroll
        for (int k16 = 0; k16 < 4; k16++) {
            int kb = ch*64 + k16*16;     // global i for A (h1)
            int kl = k16*16;             // local i in chunk buffer
            uint32_t a[4][4];
#pragma unroll
            for (int mi = 0; mi < 4; mi++) {
                uint32_t aa = sbase + ((pb + mi*16 + lm)*264 + kb + lh*8)*2;
                ldmx4(a[mi], aa);
            }
            uint32_t bb[4][4];
#pragma unroll
            for (int nj = 0; nj < 4; nj++) {
                uint32_t ba = bufb + ((ob + nj*16 + lm)*72 + kl + lh*8)*2;
                ldmx4(bb[nj], ba);
            }
#pragma unroll
            for (int mi = 0; mi < 4; mi++)
#pragma unroll
                for (int nj = 0; nj < 4; nj++) {
                    mma_fp16(acc[mi][2*nj],   a[mi], bb[nj][0], bb[nj][2]);
                    mma_fp16(acc[mi][2*nj+1], a[mi], bb[nj][1], bb[nj][3]);
                }
        }
    }
    __syncthreads();

    // ---- epilogue1: h2 = relu(D + b2) -> half, back into h1 region ----
#pragma unroll
    for (int mi = 0; mi < 4; mi++) {
#pragma unroll
        for (int ni = 0; ni < 8; ni++) {
            int p = pb + mi*16 + row;
            int o = ob + ni*8 + 2*tg;
            float bo0 = b2s[o], bo1 = b2s[o+1];
            float v00 = fmaxf(acc[mi][ni][0] + bo0, 0.f);
            float v01 = fmaxf(acc[mi][ni][1] + bo1, 0.f);
            float v10 = fmaxf(acc[mi][ni][2] + bo0, 0.f);
            float v11 = fmaxf(acc[mi][ni][3] + bo1, 0.f);
            *(__half2*)(smh + p*264 + o)     = __floats2half2_rn(v00, v01);
            *(__half2*)(smh + (p+8)*264 + o) = __floats2half2_rn(v10, v11);
        }
    }
    __syncthreads();

    // ---- GEMM2: D2[128p][64c] = h2 . W3^T (K=256), W3 already resident ----
    int pb2 = (wid & 1) * 64;
    int cb  = (wid >> 1) * 16;
    float ac2[4][2][4];
#pragma unroll
    for (int mi = 0; mi < 4; mi++)
#pragma unroll
        for (int ni = 0; ni < 2; ni++)
#pragma unroll
            for (int r = 0; r < 4; r++) ac2[mi][ni][r] = 0.f;

#pragma unroll 4
    for (int ks = 0; ks < 16; ks++) {
        int kb = ks*16;
        uint32_t a[4][4];
#pragma unroll
        for (int mi = 0; mi < 4; mi++) {
            uint32_t aa = sbase + ((pb2 + mi*16 + lm)*264 + kb + lh*8)*2;
            ldmx4(a[mi], aa);
        }
        uint32_t bb[4];
        {
            uint32_t ba = sbase + SMB_W3 + ((cb + lm)*264 + kb + lh*8)*2;
            ldmx4(bb, ba);
        }
#pragma unroll
        for (int mi = 0; mi < 4; mi++) {
            mma_fp16(ac2[mi][0], a[mi], bb[0], bb[2]);
            mma_fp16(ac2[mi][1], a[mi], bb[1], bb[3]);
        }
    }
    __syncthreads();

    // ---- stage r = D2 -> BUF region as f32 [128 p][66] ----
    {
        float* rsm = (float*)(smem + SMB_BUF);
#pragma unroll
        for (int mi = 0; mi < 4; mi++) {
#pragma unroll
            for (int ni = 0; ni < 2; ni++) {
                int p = pb2 + mi*16 + row;
                int c = cb + ni*8 + 2*tg;
                *(float2*)(rsm + p*66 + c)     = make_float2(ac2[mi][ni][0], ac2[mi][ni][1]);
                *(float2*)(rsm + (p+8)*66 + c) = make_float2(ac2[mi][ni][2], ac2[mi][ni][3]);
            }
        }
    }
    __syncthreads();

    // ---- max over k + bias + residual ----
    {
        const float* rsm = (const float*)(smem + SMB_BUF);
        for (int e = tid; e < 512; e += 256) {
            int nl = e >> 6, c = e & 63;
            float m = -3.4e38f;
#pragma unroll
            for (int kk = 0; kk < 16; kk++)
                m = fmaxf(m, rsm[(nl*16 + kk)*66 + c]);
            int oi = ((b*64 + c)*3 + d)*4096 + n0 + nl;
            out[oi] = m + b3s[c] + x[oi];
        }
    }
}

// ---------------- launch ----------------
extern "C" void kernel_launch(void* const* d_in, const int* in_sizes, int n_in,
                              void* d_out, int out_size) {
    const float* x  = (const float*)d_in[0];
    const float* W1 = (const float*)d_in[1];
    const float* b1 = (const float*)d_in[2];
    const float* W2 = (const float*)d_in[3];
    const float* b2 = (const float*)d_in[4];
    const float* W3 = (const float*)d_in[5];
    const float* b3 = (const float*)d_in[6];
    float* out = (float*)d_out;

    static bool attr_done = false;
    if (!attr_done) {
        cudaFuncSetAttribute(u_kern,   cudaFuncAttributeMaxDynamicSharedMemorySize, 74752);
        cudaFuncSetAttribute(v_mma,    cudaFuncAttributeMaxDynamicSharedMemorySize, 55296);
        cudaFuncSetAttribute(mlp2_mma, cudaFuncAttributeMaxDynamicSharedMemorySize, SMB_TOT);
        attr_done = true;
    }

    prep_w<<<64, 256>>>(W1);
    prep_w23<<<320, 256>>>(W2, W3);
    mean_k<<<2048, 256>>>(x);
    sq_k<<<32, 256>>>();
    knn_part<<<512, 128>>>();
    knn_merge<<<32, 256>>>();
    u_kern<<<768, 256, 74752>>>(x, b1);
    v_mma<<<1024, 256, 55296>>>();
    mlp2_mma<<<3072, 256, SMB_TOT>>>(x, b2, b3, out);
}